// round 9
// baseline (speedup 1.0000x reference)
#include <cuda_runtime.h>

// AffineTransformation: B=32, H=W=512, C=1, fp32.
// d_in[0] = theta [32,6] f32, d_in[1] = image [32,512,512,1] f32 -> out same shape.
//
// R4 structure (best: 19.0us) + streaming stores (__stcs) so the write-once
// output does not evict the L2-resident image (L2 holds image+output only
// marginally; evict-first stores keep gathers at L2-hit latency, not DRAM).
// Thread owns 4 vertical pixels; interior path batches all 16 gathers (MLP=16).

#define BB 32
#define HH 512
#define WW 512

__global__ __launch_bounds__(128, 10)
void affine_sample_kernel(const float* __restrict__ theta,
                          const float* __restrict__ image,
                          float* __restrict__ out)
{
    const int b = blockIdx.z;

    const float t0 = __ldg(theta + b * 6 + 0);
    const float t1 = __ldg(theta + b * 6 + 1);
    const float t2 = __ldg(theta + b * 6 + 2);
    const float t3 = __ldg(theta + b * 6 + 3);
    const float t4 = __ldg(theta + b * 6 + 4);
    const float t5 = __ldg(theta + b * 6 + 5);

    const int col  = blockIdx.x * 32 + threadIdx.x;                 // 0..511
    const int row0 = (blockIdx.y * blockDim.y + threadIdx.y) * 4;   // 4 rows/thread

    const float inv_w = 2.0f / (float)(WW - 1);
    const float inv_h = 2.0f / (float)(HH - 1);
    const float xn  = -1.0f + (float)col  * inv_w;
    const float yn0 = -1.0f + (float)row0 * inv_h;

    // Pixel-space coords at j=0; per-row derivatives: d(fx)/d(row)=t1, d(fy)/d(row)=t4.
    const float fx0 = 0.5f * (float)(WW - 1) * (t0 * xn + t1 * yn0 + t2) + 0.5f * (float)(WW - 1);
    const float fy0 = 0.5f * (float)(HH - 1) * (t3 * xn + t4 * yn0 + t5) + 0.5f * (float)(HH - 1);
    const float fx3 = fmaf(3.0f, t1, fx0);
    const float fy3 = fmaf(3.0f, t4, fy0);

    const float lox = fminf(fx0, fx3), hix = fmaxf(fx0, fx3);
    const float loy = fminf(fy0, fy3), hiy = fmaxf(fy0, fy3);

    float* const op = out + (b * HH + row0) * WW + col;   // int32-safe offset

    // (c) whole 4-row span has zero coverage -> store zeros, no gathers
    if (hix <= -1.0f || lox >= (float)WW || hiy <= -1.0f || loy >= (float)HH) {
        #pragma unroll
        for (int j = 0; j < 4; j++) __stcs(op + j * WW, 0.0f);
        return;
    }

    const float* __restrict__ img = image + b * (HH * WW);

    float r[4];

    if (lox >= 0.0f && hix < (float)(WW - 1) && loy >= 0.0f && hiy < (float)(HH - 1)) {
        // (a) fully interior: no clamps, trunc == floor, plain bilinear lerp.
        // Phase 1: addresses + fractions. Phase 2: all 16 LDGs. Phase 3: math.
        float ax[4], ay[4];
        int   base[4];
        #pragma unroll
        for (int j = 0; j < 4; j++) {
            const float fx = fmaf((float)j, t1, fx0);
            const float fy = fmaf((float)j, t4, fy0);
            const int ix = (int)fx;
            const int iy = (int)fy;
            ax[j] = fx - (float)ix;
            ay[j] = fy - (float)iy;
            base[j] = iy * WW + ix;
        }
        float va[4], vb[4], vc[4], vd[4];
        #pragma unroll
        for (int j = 0; j < 4; j++) {
            va[j] = __ldg(img + base[j]);
            vb[j] = __ldg(img + base[j] + 1);
            vc[j] = __ldg(img + base[j] + WW);
            vd[j] = __ldg(img + base[j] + WW + 1);
        }
        #pragma unroll
        for (int j = 0; j < 4; j++) {
            const float h0 = fmaf(ax[j], vb[j] - va[j], va[j]);
            const float h1 = fmaf(ax[j], vd[j] - vc[j], vc[j]);
            r[j] = __saturatef(fmaf(ay[j], h1 - h0, h0));
        }
    } else {
        // (b) border: full reference semantics (clip-then-delta, edge double-count)
        #pragma unroll
        for (int j = 0; j < 4; j++) {
            const float fx = fmaf((float)j, t1, fx0);
            const float fy = fmaf((float)j, t4, fy0);

            const float flx = floorf(fx);
            const float fly = floorf(fy);

            const float x0 = fminf(fmaxf(flx,        0.0f), (float)(WW - 1));
            const float x1 = fminf(fmaxf(flx + 1.0f, 0.0f), (float)(WW - 1));
            const float y0 = fminf(fmaxf(fly,        0.0f), (float)(HH - 1));
            const float y1 = fminf(fmaxf(fly + 1.0f, 0.0f), (float)(HH - 1));

            const float wx0 = fmaxf(0.0f, 1.0f - fabsf(fx - x0));
            const float wx1 = fmaxf(0.0f, 1.0f - fabsf(fx - x1));
            const float wy0 = fmaxf(0.0f, 1.0f - fabsf(fy - y0));
            const float wy1 = fmaxf(0.0f, 1.0f - fabsf(fy - y1));

            float v = 0.0f;
            if ((wx0 + wx1) > 0.0f && (wy0 + wy1) > 0.0f) {
                const int ix0 = (int)x0;
                const int ix1 = (int)x1;
                const int r0o = (int)y0 * WW;
                const int r1o = (int)y1 * WW;
                v = wy0 * (wx0 * __ldg(img + r0o + ix0) + wx1 * __ldg(img + r0o + ix1))
                  + wy1 * (wx0 * __ldg(img + r1o + ix0) + wx1 * __ldg(img + r1o + ix1));
            }
            r[j] = __saturatef(v);
        }
    }

    #pragma unroll
    for (int j = 0; j < 4; j++) __stcs(op + j * WW, r[j]);
}

extern "C" void kernel_launch(void* const* d_in, const int* in_sizes, int n_in,
                              void* d_out, int out_size)
{
    const float* theta = (const float*)d_in[0];
    const float* image = (const float*)d_in[1];
    float* out = (float*)d_out;

    dim3 block(32, 4, 1);                  // 128 threads; tile = 32 cols x 16 rows
    dim3 grid(WW / 32, HH / 16, BB);       // (16, 32, 32) = 16384 blocks
    affine_sample_kernel<<<grid, block>>>(theta, image, out);
}

// round 10
// speedup vs baseline: 1.2655x; 1.2655x over previous
#include <cuda_runtime.h>

// AffineTransformation: B=32, H=W=512, C=1, fp32.
// d_in[0] = theta [32,6] f32, d_in[1] = image [32,512,512,1] f32 -> out same shape.
//
// R4 structure + WIDE GATHERS: per bilinear row, one 16B-aligned float4 LDG at
// (ix & ~3) covers both needed texels when ix%4<3; ix%4==3 adds one predicated
// scalar. 16 scalar LDGs/thread -> 8 float4 + ~2 scalars => ~1.6x fewer load
// latency slots and ~2x fewer same-line wavefronts (kernel is bound by the
// SM outstanding-load capacity x L2 latency, measured ~5.4cyc/LDG effective).

#define BB 32
#define HH 512
#define WW 512

__global__ __launch_bounds__(128, 6)
void affine_sample_kernel(const float* __restrict__ theta,
                          const float* __restrict__ image,
                          float* __restrict__ out)
{
    const int b = blockIdx.z;

    const float t0 = __ldg(theta + b * 6 + 0);
    const float t1 = __ldg(theta + b * 6 + 1);
    const float t2 = __ldg(theta + b * 6 + 2);
    const float t3 = __ldg(theta + b * 6 + 3);
    const float t4 = __ldg(theta + b * 6 + 4);
    const float t5 = __ldg(theta + b * 6 + 5);

    const int col  = blockIdx.x * 32 + threadIdx.x;                 // 0..511
    const int row0 = (blockIdx.y * blockDim.y + threadIdx.y) * 4;   // 4 rows/thread

    const float inv_w = 2.0f / (float)(WW - 1);
    const float inv_h = 2.0f / (float)(HH - 1);
    const float xn  = -1.0f + (float)col  * inv_w;
    const float yn0 = -1.0f + (float)row0 * inv_h;

    // Pixel-space coords at j=0; per-row derivatives: d(fx)/d(row)=t1, d(fy)/d(row)=t4.
    const float fx0 = 0.5f * (float)(WW - 1) * (t0 * xn + t1 * yn0 + t2) + 0.5f * (float)(WW - 1);
    const float fy0 = 0.5f * (float)(HH - 1) * (t3 * xn + t4 * yn0 + t5) + 0.5f * (float)(HH - 1);
    const float fx3 = fmaf(3.0f, t1, fx0);
    const float fy3 = fmaf(3.0f, t4, fy0);

    const float lox = fminf(fx0, fx3), hix = fmaxf(fx0, fx3);
    const float loy = fminf(fy0, fy3), hiy = fmaxf(fy0, fy3);

    float* const op = out + (b * HH + row0) * WW + col;   // int32-safe

    // (c) whole 4-row span has zero coverage -> store zeros, no gathers
    if (hix <= -1.0f || lox >= (float)WW || hiy <= -1.0f || loy >= (float)HH) {
        #pragma unroll
        for (int j = 0; j < 4; j++) op[j * WW] = 0.0f;
        return;
    }

    const float* __restrict__ img = image + b * (HH * WW);

    float r[4];

    if (lox >= 0.0f && hix < (float)(WW - 1) && loy >= 0.0f && hiy < (float)(HH - 1)) {
        // (a) fully interior. Phase 1: addresses. Phase 2: all wide loads.
        // Phase 3: lane-select + lerp.
        float ax[4], ay[4];
        int   ebase[4];   // iy*WW + (ix & ~3)
        int   k[4];       // ix & 3
        #pragma unroll
        for (int j = 0; j < 4; j++) {
            const float fx = fmaf((float)j, t1, fx0);
            const float fy = fmaf((float)j, t4, fy0);
            const int ix = (int)fx;
            const int iy = (int)fy;
            ax[j] = fx - (float)ix;
            ay[j] = fy - (float)iy;
            k[j]  = ix & 3;
            ebase[j] = iy * WW + (ix & ~3);
        }
        // Wide loads: 8 x LDG.128 (16B-aligned: img 256B-aligned, e%4==0)
        float4 top[4], bot[4];
        #pragma unroll
        for (int j = 0; j < 4; j++) {
            top[j] = __ldg((const float4*)(img + ebase[j]));
            bot[j] = __ldg((const float4*)(img + ebase[j] + WW));
        }
        // Predicated extras for k==3 (need ix+1 == e+4; interior => in-bounds)
        float ext[4], exb[4];
        #pragma unroll
        for (int j = 0; j < 4; j++) {
            ext[j] = 0.0f; exb[j] = 0.0f;
            if (k[j] == 3) {
                ext[j] = __ldg(img + ebase[j] + 4);
                exb[j] = __ldg(img + ebase[j] + WW + 4);
            }
        }
        #pragma unroll
        for (int j = 0; j < 4; j++) {
            const int kk = k[j];
            const float va = kk == 0 ? top[j].x : kk == 1 ? top[j].y : kk == 2 ? top[j].z : top[j].w;
            const float vb = kk == 0 ? top[j].y : kk == 1 ? top[j].z : kk == 2 ? top[j].w : ext[j];
            const float vc = kk == 0 ? bot[j].x : kk == 1 ? bot[j].y : kk == 2 ? bot[j].z : bot[j].w;
            const float vd = kk == 0 ? bot[j].y : kk == 1 ? bot[j].z : kk == 2 ? bot[j].w : exb[j];
            const float h0 = fmaf(ax[j], vb - va, va);
            const float h1 = fmaf(ax[j], vd - vc, vc);
            r[j] = __saturatef(fmaf(ay[j], h1 - h0, h0));
        }
    } else {
        // (b) border: full reference semantics (clip-then-delta, edge double-count)
        #pragma unroll
        for (int j = 0; j < 4; j++) {
            const float fx = fmaf((float)j, t1, fx0);
            const float fy = fmaf((float)j, t4, fy0);

            const float flx = floorf(fx);
            const float fly = floorf(fy);

            const float x0 = fminf(fmaxf(flx,        0.0f), (float)(WW - 1));
            const float x1 = fminf(fmaxf(flx + 1.0f, 0.0f), (float)(WW - 1));
            const float y0 = fminf(fmaxf(fly,        0.0f), (float)(HH - 1));
            const float y1 = fminf(fmaxf(fly + 1.0f, 0.0f), (float)(HH - 1));

            const float wx0 = fmaxf(0.0f, 1.0f - fabsf(fx - x0));
            const float wx1 = fmaxf(0.0f, 1.0f - fabsf(fx - x1));
            const float wy0 = fmaxf(0.0f, 1.0f - fabsf(fy - y0));
            const float wy1 = fmaxf(0.0f, 1.0f - fabsf(fy - y1));

            float v = 0.0f;
            if ((wx0 + wx1) > 0.0f && (wy0 + wy1) > 0.0f) {
                const int ix0 = (int)x0;
                const int ix1 = (int)x1;
                const int r0o = (int)y0 * WW;
                const int r1o = (int)y1 * WW;
                v = wy0 * (wx0 * __ldg(img + r0o + ix0) + wx1 * __ldg(img + r0o + ix1))
                  + wy1 * (wx0 * __ldg(img + r1o + ix0) + wx1 * __ldg(img + r1o + ix1));
            }
            r[j] = __saturatef(v);
        }
    }

    #pragma unroll
    for (int j = 0; j < 4; j++) op[j * WW] = r[j];
}

extern "C" void kernel_launch(void* const* d_in, const int* in_sizes, int n_in,
                              void* d_out, int out_size)
{
    const float* theta = (const float*)d_in[0];
    const float* image = (const float*)d_in[1];
    float* out = (float*)d_out;

    dim3 block(32, 4, 1);                  // 128 threads; tile = 32 cols x 16 rows
    dim3 grid(WW / 32, HH / 16, BB);       // (16, 32, 32) = 16384 blocks
    affine_sample_kernel<<<grid, block>>>(theta, image, out);
}

// round 11
// speedup vs baseline: 1.5359x; 1.2137x over previous
#include <cuda_runtime.h>

// AffineTransformation: B=32, H=W=512, C=1, fp32.
// d_in[0] = theta [32,6] f32, d_in[1] = image [32,512,512,1] f32 -> out same shape.
//
// R4 core + 2D WARP PATCHES: each warp covers an 8-col x 4-row screen patch
// (lx = lane&7, ly = lane>>3), so a warp-gather's image footprint spans
// ~8|t3|+3|t4| rows (vs ~32|t3| for collinear lanes) -> breaks below the
// 32-line divergence cap that kept L1 pinned at ~52% in every prior config.
// Thread owns 4 pixels at rows ly+4j; interior path batches all 16 LDGs.

#define BB 32
#define HH 512
#define WW 512

__global__ __launch_bounds__(128, 10)
void affine_sample_kernel(const float* __restrict__ theta,
                          const float* __restrict__ image,
                          float* __restrict__ out)
{
    const int b = blockIdx.z;

    const float t0 = __ldg(theta + b * 6 + 0);
    const float t1 = __ldg(theta + b * 6 + 1);
    const float t2 = __ldg(theta + b * 6 + 2);
    const float t3 = __ldg(theta + b * 6 + 3);
    const float t4 = __ldg(theta + b * 6 + 4);
    const float t5 = __ldg(theta + b * 6 + 5);

    const int warp = threadIdx.x >> 5;
    const int lane = threadIdx.x & 31;
    const int lx   = lane & 7;          // col within warp patch
    const int ly   = lane >> 3;         // row within warp patch (0..3)

    const int col  = blockIdx.x * 32 + warp * 8 + lx;   // 0..511
    const int row0 = blockIdx.y * 16 + ly;              // pixels at row0 + 4j

    const float inv_w = 2.0f / (float)(WW - 1);
    const float inv_h = 2.0f / (float)(HH - 1);
    const float xn  = -1.0f + (float)col  * inv_w;
    const float yn0 = -1.0f + (float)row0 * inv_h;

    // Pixel-space coords at j=0. Per-j step = 4 screen rows: d(fx)=4*t1, d(fy)=4*t4.
    const float fx0 = 0.5f * (float)(WW - 1) * (t0 * xn + t1 * yn0 + t2) + 0.5f * (float)(WW - 1);
    const float fy0 = 0.5f * (float)(HH - 1) * (t3 * xn + t4 * yn0 + t5) + 0.5f * (float)(HH - 1);
    const float sjx = 4.0f * t1;
    const float sjy = 4.0f * t4;
    const float fx3 = fmaf(3.0f, sjx, fx0);
    const float fy3 = fmaf(3.0f, sjy, fy0);

    const float lox = fminf(fx0, fx3), hix = fmaxf(fx0, fx3);
    const float loy = fminf(fy0, fy3), hiy = fmaxf(fy0, fy3);

    float* const op = out + (b * HH + row0) * WW + col;   // int32-safe
    const int ostep = 4 * WW;                             // 4 rows per j

    // (c) whole span has zero coverage -> store zeros, no gathers
    if (hix <= -1.0f || lox >= (float)WW || hiy <= -1.0f || loy >= (float)HH) {
        #pragma unroll
        for (int j = 0; j < 4; j++) op[j * ostep] = 0.0f;
        return;
    }

    const float* __restrict__ img = image + b * (HH * WW);

    float r[4];

    if (lox >= 0.0f && hix < (float)(WW - 1) && loy >= 0.0f && hiy < (float)(HH - 1)) {
        // (a) fully interior: no clamps, trunc == floor, plain bilinear lerp.
        // Phase 1: addresses + fractions. Phase 2: all 16 LDGs. Phase 3: math.
        float ax[4], ay[4];
        int   base[4];
        #pragma unroll
        for (int j = 0; j < 4; j++) {
            const float fx = fmaf((float)j, sjx, fx0);
            const float fy = fmaf((float)j, sjy, fy0);
            const int ix = (int)fx;
            const int iy = (int)fy;
            ax[j] = fx - (float)ix;
            ay[j] = fy - (float)iy;
            base[j] = iy * WW + ix;
        }
        float va[4], vb[4], vc[4], vd[4];
        #pragma unroll
        for (int j = 0; j < 4; j++) {
            va[j] = __ldg(img + base[j]);
            vb[j] = __ldg(img + base[j] + 1);
            vc[j] = __ldg(img + base[j] + WW);
            vd[j] = __ldg(img + base[j] + WW + 1);
        }
        #pragma unroll
        for (int j = 0; j < 4; j++) {
            const float h0 = fmaf(ax[j], vb[j] - va[j], va[j]);
            const float h1 = fmaf(ax[j], vd[j] - vc[j], vc[j]);
            r[j] = __saturatef(fmaf(ay[j], h1 - h0, h0));
        }
    } else {
        // (b) border: full reference semantics (clip-then-delta, edge double-count)
        #pragma unroll
        for (int j = 0; j < 4; j++) {
            const float fx = fmaf((float)j, sjx, fx0);
            const float fy = fmaf((float)j, sjy, fy0);

            const float flx = floorf(fx);
            const float fly = floorf(fy);

            const float x0 = fminf(fmaxf(flx,        0.0f), (float)(WW - 1));
            const float x1 = fminf(fmaxf(flx + 1.0f, 0.0f), (float)(WW - 1));
            const float y0 = fminf(fmaxf(fly,        0.0f), (float)(HH - 1));
            const float y1 = fminf(fmaxf(fly + 1.0f, 0.0f), (float)(HH - 1));

            const float wx0 = fmaxf(0.0f, 1.0f - fabsf(fx - x0));
            const float wx1 = fmaxf(0.0f, 1.0f - fabsf(fx - x1));
            const float wy0 = fmaxf(0.0f, 1.0f - fabsf(fy - y0));
            const float wy1 = fmaxf(0.0f, 1.0f - fabsf(fy - y1));

            float v = 0.0f;
            if ((wx0 + wx1) > 0.0f && (wy0 + wy1) > 0.0f) {
                const int ix0 = (int)x0;
                const int ix1 = (int)x1;
                const int r0o = (int)y0 * WW;
                const int r1o = (int)y1 * WW;
                v = wy0 * (wx0 * __ldg(img + r0o + ix0) + wx1 * __ldg(img + r0o + ix1))
                  + wy1 * (wx0 * __ldg(img + r1o + ix0) + wx1 * __ldg(img + r1o + ix1));
            }
            r[j] = __saturatef(v);
        }
    }

    #pragma unroll
    for (int j = 0; j < 4; j++) op[j * ostep] = r[j];
}

extern "C" void kernel_launch(void* const* d_in, const int* in_sizes, int n_in,
                              void* d_out, int out_size)
{
    const float* theta = (const float*)d_in[0];
    const float* image = (const float*)d_in[1];
    float* out = (float*)d_out;

    dim3 block(128, 1, 1);                 // 4 warps; block tile = 32 cols x 16 rows
    dim3 grid(WW / 32, HH / 16, BB);       // (16, 32, 32) = 16384 blocks
    affine_sample_kernel<<<grid, block>>>(theta, image, out);
}